// round 7
// baseline (speedup 1.0000x reference)
#include <cuda_runtime.h>
#include <cstdint>

// Problem constants
#define B_ROWS 8192
#define SEQ    512
#define HDIM   256
#define TH     768          // 3*H
#define POUT   96

// Tiling
#define TILE_B        64
#define NCTA          (B_ROWS / TILE_B)   // 128
#define NTHREADS      256
#define NWARPS        8
#define ROWS_PER_WARP 8                   // TILE_B / NWARPS
#define HSTR          72                  // padded row stride of h buffer ([k][row])
#define HBUF          (HDIM * HSTR)       // floats per h buffer

// Scratch: transposed weights (written by pre-kernel each call; deterministic)
__device__ __align__(16) float g_Wt[HDIM * TH];      // Wt[k][3H] = W_hh[j][k]
__device__ __align__(16) float g_WoutT[HDIM * POUT]; // WoutT[k][p] = W_out[p][k]

// ---------------- packed f32x2 helpers ----------------
__device__ __forceinline__ void fma2(unsigned long long& d,
                                     unsigned long long a,
                                     unsigned long long b) {
    asm("fma.rn.f32x2 %0, %1, %2, %0;" : "+l"(d) : "l"(a), "l"(b));
}
__device__ __forceinline__ unsigned long long dup2(float w) {
    unsigned long long r;
    unsigned int u = __float_as_uint(w);
    asm("mov.b64 %0, {%1, %1};" : "=l"(r) : "r"(u));
    return r;
}
__device__ __forceinline__ float2 unpk(unsigned long long v) {
    unsigned int lo, hi;
    asm("mov.b64 {%0, %1}, %2;" : "=r"(lo), "=r"(hi) : "l"(v));
    return make_float2(__uint_as_float(lo), __uint_as_float(hi));
}

// ---------------- fast, accurate-enough nonlinearities ----------------
__device__ __forceinline__ float sigm(float x) {
    return __fdividef(1.0f, 1.0f + __expf(-x));
}
__device__ __forceinline__ float tanhfast(float x) {
    // 2*sigmoid(2x)-1 ; __expf handles +-inf saturation correctly
    return __fdividef(2.0f, 1.0f + __expf(-2.0f * x)) - 1.0f;
}

// ---------------- pre-kernel: transpose weights ----------------
__global__ void transpose_kernel(const float* __restrict__ W_hh,
                                 const float* __restrict__ W_out) {
    int idx = blockIdx.x * blockDim.x + threadIdx.x;
    int stride = gridDim.x * blockDim.x;
    for (int i = idx; i < HDIM * TH; i += stride) {
        int k = i / TH, j = i - k * TH;
        g_Wt[i] = W_hh[j * HDIM + k];
    }
    for (int i = idx; i < HDIM * POUT; i += stride) {
        int k = i / POUT, p = i - k * POUT;
        g_WoutT[i] = W_out[p * HDIM + k];
    }
}

// ---------------- gate epilogue per (row, hidden-unit) ----------------
__device__ __forceinline__ void gate_update(
    float a_r, float a_z, float a_n, float xval,
    float wir, float wiz, float win,
    float bir, float biz, float bin,
    float bhr, float bhz, float bhn,
    const float* __restrict__ hcp, float* __restrict__ hnp)
{
    float rg = sigm(fmaf(xval, wir, bir) + a_r + bhr);
    float zg = sigm(fmaf(xval, wiz, biz) + a_z + bhz);
    float ng = tanhfast(fmaf(xval, win, bin) + rg * (a_n + bhn));
    float hold = *hcp;
    *hnp = ng + zg * (hold - ng);
}

// ---------------- main persistent GRU kernel ----------------
__global__ void __launch_bounds__(NTHREADS, 1)
gru_kernel(const float* __restrict__ x,
           const float* __restrict__ W_ih,
           const float* __restrict__ b_ih,
           const float* __restrict__ b_hh,
           const float* __restrict__ b_out,
           float* __restrict__ out)
{
    extern __shared__ float sm[];
    // layout: [hbuf0 | hbuf1 | wih(768) | bih(768) | bhh(768)]
    float* s_wih = sm + 2 * HBUF;
    float* s_bih = s_wih + TH;
    float* s_bhh = s_bih + TH;

    const int tid  = threadIdx.x;
    const int wid  = tid >> 5;
    const int lane = tid & 31;
    const int r0   = wid * ROWS_PER_WARP;            // local row base
    const int grow = blockIdx.x * TILE_B + r0;       // global row base

    for (int i = tid; i < TH; i += NTHREADS) {
        s_wih[i] = W_ih[i];
        s_bih[i] = b_ih[i];
        s_bhh[i] = b_hh[i];
    }
    for (int i = tid; i < HBUF; i += NTHREADS) sm[i] = 0.0f;  // h0 = 0
    __syncthreads();

    for (int t = 0; t < SEQ; ++t) {
        float* hc = sm + ((t & 1) ? HBUF : 0);   // source (old h)
        float* hn = sm + ((t & 1) ? 0 : HBUF);   // destination (new h)

        // x scalar per row for this step (L1-resident along t)
        float xv[ROWS_PER_WARP];
        #pragma unroll
        for (int i = 0; i < ROWS_PER_WARP; ++i)
            xv[i] = x[(grow + i) * SEQ + t];

        #pragma unroll
        for (int pass = 0; pass < 2; ++pass) {
            const int jb = (pass * 32 + lane) * 4;   // this thread's 4 hidden cols

            // acc[pair][gate][jj] : f32x2 accumulators, rows packed in pairs
            unsigned long long acc[4][3][4];
            #pragma unroll
            for (int a = 0; a < 4; ++a)
                #pragma unroll
                for (int g = 0; g < 3; ++g)
                    #pragma unroll
                    for (int c = 0; c < 4; ++c) acc[a][g][c] = 0ull;

            #pragma unroll 4
            for (int k = 0; k < HDIM; ++k) {
                const ulonglong2* hp =
                    reinterpret_cast<const ulonglong2*>(hc + k * HSTR + r0);
                ulonglong2 hv01 = hp[0];   // rows r0..r0+3 (pairs 0,1)
                ulonglong2 hv23 = hp[1];   // rows r0+4..r0+7 (pairs 2,3)
                const float* wk = g_Wt + k * TH + jb;
                #pragma unroll
                for (int g = 0; g < 3; ++g) {
                    float4 wv = *reinterpret_cast<const float4*>(wk + g * HDIM);
                    unsigned long long w0 = dup2(wv.x);
                    unsigned long long w1 = dup2(wv.y);
                    unsigned long long w2 = dup2(wv.z);
                    unsigned long long w3 = dup2(wv.w);
                    fma2(acc[0][g][0], hv01.x, w0); fma2(acc[1][g][0], hv01.y, w0);
                    fma2(acc[2][g][0], hv23.x, w0); fma2(acc[3][g][0], hv23.y, w0);
                    fma2(acc[0][g][1], hv01.x, w1); fma2(acc[1][g][1], hv01.y, w1);
                    fma2(acc[2][g][1], hv23.x, w1); fma2(acc[3][g][1], hv23.y, w1);
                    fma2(acc[0][g][2], hv01.x, w2); fma2(acc[1][g][2], hv01.y, w2);
                    fma2(acc[2][g][2], hv23.x, w2); fma2(acc[3][g][2], hv23.y, w2);
                    fma2(acc[0][g][3], hv01.x, w3); fma2(acc[1][g][3], hv01.y, w3);
                    fma2(acc[2][g][3], hv23.x, w3); fma2(acc[3][g][3], hv23.y, w3);
                }
            }

            // gates + h update for this pass's 4 cols x 8 rows
            #pragma unroll
            for (int jj = 0; jj < 4; ++jj) {
                const int j = jb + jj;
                const float bhr = s_bhh[j];
                const float bhz = s_bhh[HDIM + j];
                const float bhn = s_bhh[2 * HDIM + j];
                const float wir = s_wih[j];
                const float wiz = s_wih[HDIM + j];
                const float win = s_wih[2 * HDIM + j];
                const float bir = s_bih[j];
                const float biz = s_bih[HDIM + j];
                const float bin = s_bih[2 * HDIM + j];
                #pragma unroll
                for (int pr = 0; pr < 4; ++pr) {
                    float2 ar = unpk(acc[pr][0][jj]);
                    float2 az = unpk(acc[pr][1][jj]);
                    float2 an = unpk(acc[pr][2][jj]);
                    const int i0 = pr * 2;
                    gate_update(ar.x, az.x, an.x, xv[i0],
                                wir, wiz, win, bir, biz, bin, bhr, bhz, bhn,
                                hc + j * HSTR + r0 + i0,
                                hn + j * HSTR + r0 + i0);
                    gate_update(ar.y, az.y, an.y, xv[i0 + 1],
                                wir, wiz, win, bir, biz, bin, bhr, bhz, bhn,
                                hc + j * HSTR + r0 + i0 + 1,
                                hn + j * HSTR + r0 + i0 + 1);
                }
            }
        }
        __syncthreads();  // all writes to hn done before next step reads it
    }

    // SEQ is even -> final h lives in buffer 0
    const float* hfin = sm;

    // out[b][p] = sum_k h[b][k] * W_out[p][k] + b_out[p]; lane -> {p, p+32, p+64}
    float oacc[ROWS_PER_WARP][3];
    #pragma unroll
    for (int i = 0; i < ROWS_PER_WARP; ++i)
        oacc[i][0] = oacc[i][1] = oacc[i][2] = 0.0f;

    for (int k = 0; k < HDIM; ++k) {
        const float w0 = g_WoutT[k * POUT + lane];
        const float w1 = g_WoutT[k * POUT + lane + 32];
        const float w2 = g_WoutT[k * POUT + lane + 64];
        #pragma unroll
        for (int i = 0; i < ROWS_PER_WARP; ++i) {
            const float hv = hfin[k * HSTR + r0 + i];
            oacc[i][0] = fmaf(hv, w0, oacc[i][0]);
            oacc[i][1] = fmaf(hv, w1, oacc[i][1]);
            oacc[i][2] = fmaf(hv, w2, oacc[i][2]);
        }
    }
    const float bo0 = b_out[lane];
    const float bo1 = b_out[lane + 32];
    const float bo2 = b_out[lane + 64];
    #pragma unroll
    for (int i = 0; i < ROWS_PER_WARP; ++i) {
        float* op = out + (size_t)(grow + i) * POUT;
        op[lane]      = oacc[i][0] + bo0;
        op[lane + 32] = oacc[i][1] + bo1;
        op[lane + 64] = oacc[i][2] + bo2;
    }
}

extern "C" void kernel_launch(void* const* d_in, const int* in_sizes, int n_in,
                              void* d_out, int out_size) {
    const float* x     = (const float*)d_in[0];
    const float* W_ih  = (const float*)d_in[1];
    const float* W_hh  = (const float*)d_in[2];
    const float* b_ih  = (const float*)d_in[3];
    const float* b_hh  = (const float*)d_in[4];
    const float* W_out = (const float*)d_in[5];
    const float* b_out = (const float*)d_in[6];
    float* out = (float*)d_out;

    const size_t smem = (size_t)(2 * HBUF + 3 * TH) * sizeof(float); // ~157 KB
    cudaFuncSetAttribute(gru_kernel,
                         cudaFuncAttributeMaxDynamicSharedMemorySize, (int)smem);

    transpose_kernel<<<256, 256>>>(W_hh, W_out);
    gru_kernel<<<NCTA, NTHREADS, smem>>>(x, W_ih, b_ih, b_hh, b_out, out);
}

// round 8
// speedup vs baseline: 1.0595x; 1.0595x over previous
#include <cuda_runtime.h>
#include <cstdint>

// Problem constants
#define B_ROWS 8192
#define SEQ    512
#define HDIM   256
#define TH     768          // 3*H
#define POUT   96

// Tiling
#define TILE_B   64
#define NCTA     (B_ROWS / TILE_B)   // 128
#define NTHREADS 512
#define NWARPS   16
#define RPW      4                   // rows per warp
#define KW       64                  // words per hidden-unit row of h buffer (=TILE_B)
#define HBUF     (HDIM * KW)         // 16384 floats per h buffer

// Scratch: transposed weights (written by pre-kernel each call; deterministic)
__device__ __align__(16) float g_Wt[HDIM * TH];      // Wt[k][3H] = W_hh[j][k]
__device__ __align__(16) float g_WoutT[HDIM * POUT]; // WoutT[k][p] = W_out[p][k]

// ---------------- packed f32x2 helpers ----------------
__device__ __forceinline__ void fma2(unsigned long long& d,
                                     unsigned long long a,
                                     unsigned long long b) {
    asm("fma.rn.f32x2 %0, %1, %2, %0;" : "+l"(d) : "l"(a), "l"(b));
}
__device__ __forceinline__ unsigned long long dup2(float w) {
    unsigned long long r;
    unsigned int u = __float_as_uint(w);
    asm("mov.b64 %0, {%1, %1};" : "=l"(r) : "r"(u));
    return r;
}
__device__ __forceinline__ float2 unpk(unsigned long long v) {
    unsigned int lo, hi;
    asm("mov.b64 {%0, %1}, %2;" : "=r"(lo), "=r"(hi) : "l"(v));
    return make_float2(__uint_as_float(lo), __uint_as_float(hi));
}

// ---------------- fast, accurate-enough nonlinearities ----------------
__device__ __forceinline__ float sigm(float x) {
    return __fdividef(1.0f, 1.0f + __expf(-x));
}
__device__ __forceinline__ float tanhfast(float x) {
    return __fdividef(2.0f, 1.0f + __expf(-2.0f * x)) - 1.0f;
}

// swizzled word offset of warp `wid`'s 4-row float4 in hidden-unit column `k`
__device__ __forceinline__ int hswz(int k, int wid) {
    return k * KW + (((wid ^ ((k >> 2) & 15))) << 2);
}

// ---------------- pre-kernel: transpose weights ----------------
__global__ void transpose_kernel(const float* __restrict__ W_hh,
                                 const float* __restrict__ W_out) {
    int idx = blockIdx.x * blockDim.x + threadIdx.x;
    int stride = gridDim.x * blockDim.x;
    for (int i = idx; i < HDIM * TH; i += stride) {
        int k = i / TH, j = i - k * TH;
        g_Wt[i] = W_hh[j * HDIM + k];
    }
    for (int i = idx; i < HDIM * POUT; i += stride) {
        int k = i / POUT, p = i - k * POUT;
        g_WoutT[i] = W_out[p * HDIM + k];
    }
}

// gate update: returns h_new
__device__ __forceinline__ float gate(
    float a_r, float a_z, float a_n, float xval, float hold,
    float wir, float wiz, float win,
    float bir, float biz, float bin,
    float bhr, float bhz, float bhn)
{
    float rg = sigm(fmaf(xval, wir, bir) + a_r + bhr);
    float zg = sigm(fmaf(xval, wiz, biz) + a_z + bhz);
    float ng = tanhfast(fmaf(xval, win, bin) + rg * (a_n + bhn));
    return ng + zg * (hold - ng);
}

// ---------------- main persistent GRU kernel ----------------
__global__ void __launch_bounds__(NTHREADS, 1)
gru_kernel(const float* __restrict__ x,
           const float* __restrict__ W_ih,
           const float* __restrict__ b_ih,
           const float* __restrict__ b_hh,
           const float* __restrict__ b_out,
           float* __restrict__ out)
{
    extern __shared__ float sm[];
    // layout: [hbuf0 | hbuf1 | wih(768) | bih(768) | bhh(768)]
    float* s_wih = sm + 2 * HBUF;
    float* s_bih = s_wih + TH;
    float* s_bhh = s_bih + TH;

    const int tid  = threadIdx.x;
    const int wid  = tid >> 5;
    const int lane = tid & 31;
    const int grow = blockIdx.x * TILE_B + wid * RPW;  // global row base (4 rows)

    for (int i = tid; i < TH; i += NTHREADS) {
        s_wih[i] = W_ih[i];
        s_bih[i] = b_ih[i];
        s_bhh[i] = b_hh[i];
    }
    for (int i = tid; i < 2 * HBUF; i += NTHREADS) sm[i] = 0.0f;  // h0 = 0
    __syncthreads();   // only block-wide sync needed; h rows are warp-private after this

    for (int t = 0; t < SEQ; ++t) {
        float* hc = sm + ((t & 1) ? HBUF : 0);   // source (old h)
        float* hn = sm + ((t & 1) ? 0 : HBUF);   // destination (new h)

        // x scalar per row for this step (broadcast LDG, L1-resident along t)
        float xv[RPW];
        #pragma unroll
        for (int i = 0; i < RPW; ++i)
            xv[i] = x[(grow + i) * SEQ + t];

        #pragma unroll
        for (int pass = 0; pass < 2; ++pass) {
            const int jb = (pass * 32 + lane) * 4;   // this thread's 4 hidden cols

            // acc[row][gate][colpair]: f32x2 accumulators, COLS packed in pairs
            unsigned long long acc[RPW][3][2];
            #pragma unroll
            for (int r = 0; r < RPW; ++r)
                #pragma unroll
                for (int g = 0; g < 3; ++g) {
                    acc[r][g][0] = 0ull; acc[r][g][1] = 0ull;
                }

            const float* wp = g_Wt + jb;
            // prefetch k = 0
            ulonglong2 w0 = *reinterpret_cast<const ulonglong2*>(wp);
            ulonglong2 w1 = *reinterpret_cast<const ulonglong2*>(wp + HDIM);
            ulonglong2 w2 = *reinterpret_cast<const ulonglong2*>(wp + 2 * HDIM);
            float4 hv = *reinterpret_cast<const float4*>(hc + hswz(0, wid));

            #pragma unroll 2
            for (int k = 0; k < HDIM; ++k) {
                ulonglong2 nw0, nw1, nw2;
                float4 nhv;
                if (k + 1 < HDIM) {
                    const float* wq = wp + (k + 1) * TH;
                    nw0 = *reinterpret_cast<const ulonglong2*>(wq);
                    nw1 = *reinterpret_cast<const ulonglong2*>(wq + HDIM);
                    nw2 = *reinterpret_cast<const ulonglong2*>(wq + 2 * HDIM);
                    nhv = *reinterpret_cast<const float4*>(hc + hswz(k + 1, wid));
                }
                unsigned long long h0 = dup2(hv.x);
                unsigned long long h1 = dup2(hv.y);
                unsigned long long h2 = dup2(hv.z);
                unsigned long long h3 = dup2(hv.w);

                fma2(acc[0][0][0], h0, w0.x); fma2(acc[0][0][1], h0, w0.y);
                fma2(acc[1][0][0], h1, w0.x); fma2(acc[1][0][1], h1, w0.y);
                fma2(acc[2][0][0], h2, w0.x); fma2(acc[2][0][1], h2, w0.y);
                fma2(acc[3][0][0], h3, w0.x); fma2(acc[3][0][1], h3, w0.y);

                fma2(acc[0][1][0], h0, w1.x); fma2(acc[0][1][1], h0, w1.y);
                fma2(acc[1][1][0], h1, w1.x); fma2(acc[1][1][1], h1, w1.y);
                fma2(acc[2][1][0], h2, w1.x); fma2(acc[2][1][1], h2, w1.y);
                fma2(acc[3][1][0], h3, w1.x); fma2(acc[3][1][1], h3, w1.y);

                fma2(acc[0][2][0], h0, w2.x); fma2(acc[0][2][1], h0, w2.y);
                fma2(acc[1][2][0], h1, w2.x); fma2(acc[1][2][1], h1, w2.y);
                fma2(acc[2][2][0], h2, w2.x); fma2(acc[2][2][1], h2, w2.y);
                fma2(acc[3][2][0], h3, w2.x); fma2(acc[3][2][1], h3, w2.y);

                hv = nhv; w0 = nw0; w1 = nw1; w2 = nw2;
            }

            // epilogue: 4 cols x 4 rows; conflict-free swizzled float4 LDS/STS
            #pragma unroll
            for (int cc = 0; cc < 4; ++cc) {
                const int c = cc >> 1;           // colpair
                const int j = jb + cc;

                float gr[RPW], gz[RPW], gn[RPW];
                #pragma unroll
                for (int r = 0; r < RPW; ++r) {
                    float2 vr = unpk(acc[r][0][c]);
                    float2 vz = unpk(acc[r][1][c]);
                    float2 vn = unpk(acc[r][2][c]);
                    gr[r] = (cc & 1) ? vr.y : vr.x;
                    gz[r] = (cc & 1) ? vz.y : vz.x;
                    gn[r] = (cc & 1) ? vn.y : vn.x;
                }

                const float bhr = s_bhh[j];
                const float bhz = s_bhh[HDIM + j];
                const float bhn = s_bhh[2 * HDIM + j];
                const float wir = s_wih[j];
                const float wiz = s_wih[HDIM + j];
                const float win = s_wih[2 * HDIM + j];
                const float bir = s_bih[j];
                const float biz = s_bih[HDIM + j];
                const float bin = s_bih[2 * HDIM + j];

                const int off = hswz(j, wid);
                float4 hold = *reinterpret_cast<const float4*>(hc + off);
                float4 hnew;
                hnew.x = gate(gr[0], gz[0], gn[0], xv[0], hold.x,
                              wir, wiz, win, bir, biz, bin, bhr, bhz, bhn);
                hnew.y = gate(gr[1], gz[1], gn[1], xv[1], hold.y,
                              wir, wiz, win, bir, biz, bin, bhr, bhz, bhn);
                hnew.z = gate(gr[2], gz[2], gn[2], xv[2], hold.z,
                              wir, wiz, win, bir, biz, bin, bhr, bhz, bhn);
                hnew.w = gate(gr[3], gz[3], gn[3], xv[3], hold.w,
                              wir, wiz, win, bir, biz, bin, bhr, bhz, bhn);
                *reinterpret_cast<float4*>(hn + off) = hnew;
            }
        }
        __syncwarp();  // h rows are warp-private: warp-level sync suffices
    }

    // SEQ even -> final h lives in buffer 0 (warp-private rows, no block sync needed)
    const float* hfin = sm;

    // out[b][p] = sum_k h[b][k] * W_out[p][k] + b_out[p]; lane -> {p, p+32, p+64}
    float oacc[RPW][3];
    #pragma unroll
    for (int i = 0; i < RPW; ++i)
        oacc[i][0] = oacc[i][1] = oacc[i][2] = 0.0f;

    for (int k = 0; k < HDIM; ++k) {
        const float w0 = g_WoutT[k * POUT + lane];
        const float w1 = g_WoutT[k * POUT + lane + 32];
        const float w2 = g_WoutT[k * POUT + lane + 64];
        float4 hvf = *reinterpret_cast<const float4*>(hfin + hswz(k, wid));
        const float hr[RPW] = {hvf.x, hvf.y, hvf.z, hvf.w};
        #pragma unroll
        for (int i = 0; i < RPW; ++i) {
            oacc[i][0] = fmaf(hr[i], w0, oacc[i][0]);
            oacc[i][1] = fmaf(hr[i], w1, oacc[i][1]);
            oacc[i][2] = fmaf(hr[i], w2, oacc[i][2]);
        }
    }
    const float bo0 = b_out[lane];
    const float bo1 = b_out[lane + 32];
    const float bo2 = b_out[lane + 64];
    #pragma unroll
    for (int i = 0; i < RPW; ++i) {
        float* op = out + (size_t)(grow + i) * POUT;
        op[lane]      = oacc[i][0] + bo0;
        op[lane + 32] = oacc[i][1] + bo1;
        op[lane + 64] = oacc[i][2] + bo2;
    }
}

extern "C" void kernel_launch(void* const* d_in, const int* in_sizes, int n_in,
                              void* d_out, int out_size) {
    const float* x     = (const float*)d_in[0];
    const float* W_ih  = (const float*)d_in[1];
    const float* W_hh  = (const float*)d_in[2];
    const float* b_ih  = (const float*)d_in[3];
    const float* b_hh  = (const float*)d_in[4];
    const float* W_out = (const float*)d_in[5];
    const float* b_out = (const float*)d_in[6];
    float* out = (float*)d_out;

    const size_t smem = (size_t)(2 * HBUF + 3 * TH) * sizeof(float); // ~137 KB
    cudaFuncSetAttribute(gru_kernel,
                         cudaFuncAttributeMaxDynamicSharedMemorySize, (int)smem);

    transpose_kernel<<<256, 256>>>(W_hh, W_out);
    gru_kernel<<<NCTA, NTHREADS, smem>>>(x, W_ih, b_ih, b_hh, b_out, out);
}

// round 9
// speedup vs baseline: 1.0598x; 1.0004x over previous
#include <cuda_runtime.h>
#include <cstdint>

// Problem constants
#define B_ROWS 8192
#define SEQ    512
#define HDIM   256
#define TH     768          // 3*H
#define POUT   96

// Tiling
#define TILE_B   64
#define NCTA     (B_ROWS / TILE_B)   // 128
#define NTHREADS 512
#define NWARPS   16
#define RPW      4                   // rows per warp
#define KW       64                  // words per hidden-unit row of h buffer (=TILE_B)
#define HBUF     (HDIM * KW)         // 16384 floats per h buffer

// Scratch: transposed weights (written by pre-kernel each call; deterministic)
__device__ __align__(16) float g_Wt[HDIM * TH];      // Wt[k][3H] = W_hh[j][k]
__device__ __align__(16) float g_WoutT[HDIM * POUT]; // WoutT[k][p] = W_out[p][k]

// ---------------- packed f32x2 helpers ----------------
__device__ __forceinline__ void fma2(unsigned long long& d,
                                     unsigned long long a,
                                     unsigned long long b) {
    asm("fma.rn.f32x2 %0, %1, %2, %0;" : "+l"(d) : "l"(a), "l"(b));
}
__device__ __forceinline__ unsigned long long dup2(float w) {
    unsigned long long r;
    unsigned int u = __float_as_uint(w);
    asm("mov.b64 %0, {%1, %1};" : "=l"(r) : "r"(u));
    return r;
}
__device__ __forceinline__ float2 unpk(unsigned long long v) {
    unsigned int lo, hi;
    asm("mov.b64 {%0, %1}, %2;" : "=r"(lo), "=r"(hi) : "l"(v));
    return make_float2(__uint_as_float(lo), __uint_as_float(hi));
}

// ---------------- fast, accurate-enough nonlinearities ----------------
__device__ __forceinline__ float sigm(float x) {
    return __fdividef(1.0f, 1.0f + __expf(-x));
}
__device__ __forceinline__ float tanhfast(float x) {
    return __fdividef(2.0f, 1.0f + __expf(-2.0f * x)) - 1.0f;
}

// swizzled word offset of warp `wid`'s 4-row float4 in hidden-unit column `k`
__device__ __forceinline__ int hswz(int k, int wid) {
    return k * KW + (((wid ^ ((k >> 2) & 15))) << 2);
}

// ---------------- pre-kernel: transpose weights ----------------
__global__ void transpose_kernel(const float* __restrict__ W_hh,
                                 const float* __restrict__ W_out) {
    int idx = blockIdx.x * blockDim.x + threadIdx.x;
    int stride = gridDim.x * blockDim.x;
    for (int i = idx; i < HDIM * TH; i += stride) {
        int k = i / TH, j = i - k * TH;
        g_Wt[i] = W_hh[j * HDIM + k];
    }
    for (int i = idx; i < HDIM * POUT; i += stride) {
        int k = i / POUT, p = i - k * POUT;
        g_WoutT[i] = W_out[p * HDIM + k];
    }
}

// gate update: returns h_new
__device__ __forceinline__ float gate(
    float a_r, float a_z, float a_n, float xval, float hold,
    float wir, float wiz, float win,
    float bir, float biz, float bin,
    float bhr, float bhz, float bhn)
{
    float rg = sigm(fmaf(xval, wir, bir) + a_r + bhr);
    float zg = sigm(fmaf(xval, wiz, biz) + a_z + bhz);
    float ng = tanhfast(fmaf(xval, win, bin) + rg * (a_n + bhn));
    return ng + zg * (hold - ng);
}

// ---------------- main persistent GRU kernel ----------------
__global__ void __launch_bounds__(NTHREADS, 1)
gru_kernel(const float* __restrict__ x,
           const float* __restrict__ W_ih,
           const float* __restrict__ b_ih,
           const float* __restrict__ b_hh,
           const float* __restrict__ b_out,
           float* __restrict__ out)
{
    extern __shared__ float sm[];
    // layout: [hbuf0 | hbuf1 | wih(768) | bih(768) | bhh(768)]
    float* s_wih = sm + 2 * HBUF;
    float* s_bih = s_wih + TH;
    float* s_bhh = s_bih + TH;

    const int tid  = threadIdx.x;
    const int wid  = tid >> 5;
    const int lane = tid & 31;
    const int grow = blockIdx.x * TILE_B + wid * RPW;  // global row base (4 rows)

    for (int i = tid; i < TH; i += NTHREADS) {
        s_wih[i] = W_ih[i];
        s_bih[i] = b_ih[i];
        s_bhh[i] = b_hh[i];
    }
    for (int i = tid; i < 2 * HBUF; i += NTHREADS) sm[i] = 0.0f;  // h0 = 0
    __syncthreads();   // only block-wide sync needed; h rows are warp-private after this

    for (int t = 0; t < SEQ; ++t) {
        float* hc = sm + ((t & 1) ? HBUF : 0);   // source (old h)
        float* hn = sm + ((t & 1) ? 0 : HBUF);   // destination (new h)

        // x scalar per row for this step (broadcast LDG, L1-resident along t)
        float xv[RPW];
        #pragma unroll
        for (int i = 0; i < RPW; ++i)
            xv[i] = x[(grow + i) * SEQ + t];

        #pragma unroll
        for (int pass = 0; pass < 2; ++pass) {
            const int jb = (pass * 32 + lane) * 4;   // this thread's 4 hidden cols

            // acc[row][gate][colpair]: f32x2 accumulators, COLS packed in pairs
            unsigned long long acc[RPW][3][2];
            #pragma unroll
            for (int r = 0; r < RPW; ++r)
                #pragma unroll
                for (int g = 0; g < 3; ++g) {
                    acc[r][g][0] = 0ull; acc[r][g][1] = 0ull;
                }

            const float* wp = g_Wt + jb;
            // prefetch k = 0
            ulonglong2 w0 = *reinterpret_cast<const ulonglong2*>(wp);
            ulonglong2 w1 = *reinterpret_cast<const ulonglong2*>(wp + HDIM);
            ulonglong2 w2 = *reinterpret_cast<const ulonglong2*>(wp + 2 * HDIM);
            float4 hv = *reinterpret_cast<const float4*>(hc + hswz(0, wid));

            #pragma unroll 2
            for (int k = 0; k < HDIM; ++k) {
                ulonglong2 nw0, nw1, nw2;
                float4 nhv;
                if (k + 1 < HDIM) {
                    const float* wq = wp + (k + 1) * TH;
                    nw0 = *reinterpret_cast<const ulonglong2*>(wq);
                    nw1 = *reinterpret_cast<const ulonglong2*>(wq + HDIM);
                    nw2 = *reinterpret_cast<const ulonglong2*>(wq + 2 * HDIM);
                    nhv = *reinterpret_cast<const float4*>(hc + hswz(k + 1, wid));
                }
                unsigned long long h0 = dup2(hv.x);
                unsigned long long h1 = dup2(hv.y);
                unsigned long long h2 = dup2(hv.z);
                unsigned long long h3 = dup2(hv.w);

                fma2(acc[0][0][0], h0, w0.x); fma2(acc[0][0][1], h0, w0.y);
                fma2(acc[1][0][0], h1, w0.x); fma2(acc[1][0][1], h1, w0.y);
                fma2(acc[2][0][0], h2, w0.x); fma2(acc[2][0][1], h2, w0.y);
                fma2(acc[3][0][0], h3, w0.x); fma2(acc[3][0][1], h3, w0.y);

                fma2(acc[0][1][0], h0, w1.x); fma2(acc[0][1][1], h0, w1.y);
                fma2(acc[1][1][0], h1, w1.x); fma2(acc[1][1][1], h1, w1.y);
                fma2(acc[2][1][0], h2, w1.x); fma2(acc[2][1][1], h2, w1.y);
                fma2(acc[3][1][0], h3, w1.x); fma2(acc[3][1][1], h3, w1.y);

                fma2(acc[0][2][0], h0, w2.x); fma2(acc[0][2][1], h0, w2.y);
                fma2(acc[1][2][0], h1, w2.x); fma2(acc[1][2][1], h1, w2.y);
                fma2(acc[2][2][0], h2, w2.x); fma2(acc[2][2][1], h2, w2.y);
                fma2(acc[3][2][0], h3, w2.x); fma2(acc[3][2][1], h3, w2.y);

                hv = nhv; w0 = nw0; w1 = nw1; w2 = nw2;
            }

            // epilogue: 4 cols x 4 rows; conflict-free swizzled float4 LDS/STS
            #pragma unroll
            for (int cc = 0; cc < 4; ++cc) {
                const int c = cc >> 1;           // colpair
                const int j = jb + cc;

                float gr[RPW], gz[RPW], gn[RPW];
                #pragma unroll
                for (int r = 0; r < RPW; ++r) {
                    float2 vr = unpk(acc[r][0][c]);
                    float2 vz = unpk(acc[r][1][c]);
                    float2 vn = unpk(acc[r][2][c]);
                    gr[r] = (cc & 1) ? vr.y : vr.x;
                    gz[r] = (cc & 1) ? vz.y : vz.x;
                    gn[r] = (cc & 1) ? vn.y : vn.x;
                }

                const float bhr = s_bhh[j];
                const float bhz = s_bhh[HDIM + j];
                const float bhn = s_bhh[2 * HDIM + j];
                const float wir = s_wih[j];
                const float wiz = s_wih[HDIM + j];
                const float win = s_wih[2 * HDIM + j];
                const float bir = s_bih[j];
                const float biz = s_bih[HDIM + j];
                const float bin = s_bih[2 * HDIM + j];

                const int off = hswz(j, wid);
                float4 hold = *reinterpret_cast<const float4*>(hc + off);
                float4 hnew;
                hnew.x = gate(gr[0], gz[0], gn[0], xv[0], hold.x,
                              wir, wiz, win, bir, biz, bin, bhr, bhz, bhn);
                hnew.y = gate(gr[1], gz[1], gn[1], xv[1], hold.y,
                              wir, wiz, win, bir, biz, bin, bhr, bhz, bhn);
                hnew.z = gate(gr[2], gz[2], gn[2], xv[2], hold.z,
                              wir, wiz, win, bir, biz, bin, bhr, bhz, bhn);
                hnew.w = gate(gr[3], gz[3], gn[3], xv[3], hold.w,
                              wir, wiz, win, bir, biz, bin, bhr, bhz, bhn);
                *reinterpret_cast<float4*>(hn + off) = hnew;
            }
        }
        __syncwarp();  // h rows are warp-private: warp-level sync suffices
    }

    // SEQ even -> final h lives in buffer 0 (warp-private rows, no block sync needed)
    const float* hfin = sm;

    // out[b][p] = sum_k h[b][k] * W_out[p][k] + b_out[p]; lane -> {p, p+32, p+64}
    float oacc[RPW][3];
    #pragma unroll
    for (int i = 0; i < RPW; ++i)
        oacc[i][0] = oacc[i][1] = oacc[i][2] = 0.0f;

    for (int k = 0; k < HDIM; ++k) {
        const float w0 = g_WoutT[k * POUT + lane];
        const float w1 = g_WoutT[k * POUT + lane + 32];
        const float w2 = g_WoutT[k * POUT + lane + 64];
        float4 hvf = *reinterpret_cast<const float4*>(hfin + hswz(k, wid));
        const float hr[RPW] = {hvf.x, hvf.y, hvf.z, hvf.w};
        #pragma unroll
        for (int i = 0; i < RPW; ++i) {
            oacc[i][0] = fmaf(hr[i], w0, oacc[i][0]);
            oacc[i][1] = fmaf(hr[i], w1, oacc[i][1]);
            oacc[i][2] = fmaf(hr[i], w2, oacc[i][2]);
        }
    }
    const float bo0 = b_out[lane];
    const float bo1 = b_out[lane + 32];
    const float bo2 = b_out[lane + 64];
    #pragma unroll
    for (int i = 0; i < RPW; ++i) {
        float* op = out + (size_t)(grow + i) * POUT;
        op[lane]      = oacc[i][0] + bo0;
        op[lane + 32] = oacc[i][1] + bo1;
        op[lane + 64] = oacc[i][2] + bo2;
    }
}

extern "C" void kernel_launch(void* const* d_in, const int* in_sizes, int n_in,
                              void* d_out, int out_size) {
    const float* x     = (const float*)d_in[0];
    const float* W_ih  = (const float*)d_in[1];
    const float* W_hh  = (const float*)d_in[2];
    const float* b_ih  = (const float*)d_in[3];
    const float* b_hh  = (const float*)d_in[4];
    const float* W_out = (const float*)d_in[5];
    const float* b_out = (const float*)d_in[6];
    float* out = (float*)d_out;

    const size_t smem = (size_t)(2 * HBUF + 3 * TH) * sizeof(float); // ~137 KB
    cudaFuncSetAttribute(gru_kernel,
                         cudaFuncAttributeMaxDynamicSharedMemorySize, (int)smem);

    transpose_kernel<<<256, 256>>>(W_hh, W_out);
    gru_kernel<<<NCTA, NTHREADS, smem>>>(x, W_ih, b_ih, b_hh, b_out, out);
}

// round 10
// speedup vs baseline: 1.1199x; 1.0567x over previous
#include <cuda_runtime.h>
#include <cstdint>

// Problem constants
#define B_ROWS 8192
#define SEQ    512
#define HDIM   256
#define TH     768          // 3*H
#define POUT   96

// Tiling
#define TILE_B   64
#define NCTA     (B_ROWS / TILE_B)   // 128
#define NTHREADS 512
#define KW       64                  // words per hidden-unit column of h ([k][row])
#define HBUF     (HDIM * KW)         // 16384 floats per h buffer
#define PARW     4096                // swizzled gate-param table (words)

// Scratch: transposed weights (written by pre-kernel each call; deterministic)
__device__ __align__(16) float g_Wt[HDIM * TH];      // Wt[k][3H] = W_hh[j][k]
__device__ __align__(16) float g_WoutT[HDIM * POUT]; // WoutT[k][p] = W_out[p][k]

// ---------------- packed f32x2 helpers ----------------
__device__ __forceinline__ void fma2(unsigned long long& d,
                                     unsigned long long a,
                                     unsigned long long b) {
    asm("fma.rn.f32x2 %0, %1, %2, %0;" : "+l"(d) : "l"(a), "l"(b));
}
__device__ __forceinline__ unsigned long long dup2(float w) {
    unsigned long long r;
    unsigned int u = __float_as_uint(w);
    asm("mov.b64 %0, {%1, %1};" : "=l"(r) : "r"(u));
    return r;
}
__device__ __forceinline__ float2 unpk(unsigned long long v) {
    unsigned int lo, hi;
    asm("mov.b64 {%0, %1}, %2;" : "=r"(lo), "=r"(hi) : "l"(v));
    return make_float2(__uint_as_float(lo), __uint_as_float(hi));
}

// ---------------- fast, accurate-enough nonlinearities ----------------
__device__ __forceinline__ float sigm(float x) {
    return __fdividef(1.0f, 1.0f + __expf(-x));
}
__device__ __forceinline__ float tanhfast(float x) {
    return __fdividef(2.0f, 1.0f + __expf(-2.0f * x)) - 1.0f;
}

// word offset of the float4 holding rows [rowgrp*4 .. +4) of hidden column k
__device__ __forceinline__ int hoff(int k, int rowgrp) {
    return k * KW + ((rowgrp ^ ((k >> 2) & 15)) << 2);
}
// base word of the 7-float param record of hidden unit j (bank-swizzled)
__device__ __forceinline__ int parbase(int j) {
    int c = j >> 2;
    return c * 64 + ((c & 7) << 2) + ((j & 3) << 3);
}

// ---------------- pre-kernel: transpose weights ----------------
__global__ void transpose_kernel(const float* __restrict__ W_hh,
                                 const float* __restrict__ W_out) {
    int idx = blockIdx.x * blockDim.x + threadIdx.x;
    int stride = gridDim.x * blockDim.x;
    for (int i = idx; i < HDIM * TH; i += stride) {
        int k = i / TH, j = i - k * TH;
        g_Wt[i] = W_hh[j * HDIM + k];
    }
    for (int i = idx; i < HDIM * POUT; i += stride) {
        int k = i / POUT, p = i - k * POUT;
        g_WoutT[i] = W_out[p * HDIM + k];
    }
}

// gate update with pre-packed params p0={wir,wiz,win,br}, p1={bz,bin,bhn,_}
__device__ __forceinline__ float gate(
    float a_r, float a_z, float a_n, float xval, float hold,
    float4 p0, float4 p1)
{
    float rg = sigm(fmaf(xval, p0.x, p0.w) + a_r);
    float zg = sigm(fmaf(xval, p0.y, p1.x) + a_z);
    float ng = tanhfast(fmaf(xval, p0.z, p1.y) + rg * (a_n + p1.z));
    return ng + zg * (hold - ng);
}

#define FMABLK(HV, W0, W1, W2)                                              \
    do {                                                                    \
        unsigned long long h0 = dup2((HV).x), h1 = dup2((HV).y);            \
        unsigned long long h2 = dup2((HV).z), h3 = dup2((HV).w);            \
        fma2(acc[0][0][0], h0, (W0).x); fma2(acc[0][0][1], h0, (W0).y);     \
        fma2(acc[1][0][0], h1, (W0).x); fma2(acc[1][0][1], h1, (W0).y);     \
        fma2(acc[2][0][0], h2, (W0).x); fma2(acc[2][0][1], h2, (W0).y);     \
        fma2(acc[3][0][0], h3, (W0).x); fma2(acc[3][0][1], h3, (W0).y);     \
        fma2(acc[0][1][0], h0, (W1).x); fma2(acc[0][1][1], h0, (W1).y);     \
        fma2(acc[1][1][0], h1, (W1).x); fma2(acc[1][1][1], h1, (W1).y);     \
        fma2(acc[2][1][0], h2, (W1).x); fma2(acc[2][1][1], h2, (W1).y);     \
        fma2(acc[3][1][0], h3, (W1).x); fma2(acc[3][1][1], h3, (W1).y);     \
        fma2(acc[0][2][0], h0, (W2).x); fma2(acc[0][2][1], h0, (W2).y);     \
        fma2(acc[1][2][0], h1, (W2).x); fma2(acc[1][2][1], h1, (W2).y);     \
        fma2(acc[2][2][0], h2, (W2).x); fma2(acc[2][2][1], h2, (W2).y);     \
        fma2(acc[3][2][0], h3, (W2).x); fma2(acc[3][2][1], h3, (W2).y);     \
    } while (0)

// ---------------- main persistent GRU kernel ----------------
__global__ void __launch_bounds__(NTHREADS, 1)
gru_kernel(const float* __restrict__ x,
           const float* __restrict__ W_ih,
           const float* __restrict__ b_ih,
           const float* __restrict__ b_hh,
           const float* __restrict__ b_out,
           float* __restrict__ out)
{
    extern __shared__ float sm[];
    float* s_par = sm + 2 * HBUF;

    const int tid    = threadIdx.x;
    const int wid    = tid >> 5;
    const int lane   = tid & 31;
    const int rg     = wid >> 2;        // row group 0..3 (warpgroup)
    const int hg     = wid & 3;         // hidden group 0..3 (=SMSP)
    const int rsub   = lane & 3;        // row subchunk within group
    const int csub   = lane >> 2;       // hidden subchunk 0..7
    const int rowgrp = rg * 4 + rsub;   // 0..15 -> rows rowgrp*4..+4
    const int grow   = blockIdx.x * TILE_B + rowgrp * 4;

    // init gate-param table (biases pre-combined) and h buffers
    for (int j = tid; j < HDIM; j += NTHREADS) {
        int pb = parbase(j);
        s_par[pb + 0] = W_ih[j];
        s_par[pb + 1] = W_ih[HDIM + j];
        s_par[pb + 2] = W_ih[2 * HDIM + j];
        s_par[pb + 3] = b_ih[j] + b_hh[j];
        s_par[pb + 4] = b_ih[HDIM + j] + b_hh[HDIM + j];
        s_par[pb + 5] = b_ih[2 * HDIM + j];
        s_par[pb + 6] = b_hh[2 * HDIM + j];
    }
    for (int i = tid; i < 2 * HBUF; i += NTHREADS) sm[i] = 0.0f;  // h0 = 0
    __syncthreads();

    const int barid = 1 + rg;   // named barrier per 128-thread row-group

    for (int t = 0; t < SEQ; ++t) {
        float* hc = sm + ((t & 1) ? HBUF : 0);
        float* hn = sm + ((t & 1) ? 0 : HBUF);

        float xv[4];
        #pragma unroll
        for (int r = 0; r < 4; ++r) xv[r] = x[(grow + r) * SEQ + t];

        #pragma unroll
        for (int pass = 0; pass < 2; ++pass) {
            const float* wb = g_Wt + pass * 128 + hg * 32 + csub * 4;

            unsigned long long acc[4][3][2];
            #pragma unroll
            for (int r = 0; r < 4; ++r)
                #pragma unroll
                for (int g = 0; g < 3; ++g) {
                    acc[r][g][0] = 0ull; acc[r][g][1] = 0ull;
                }

            // depth-2 software pipeline: weights from GMEM(L1/L2), h from SMEM
            ulonglong2 wA0, wA1, wA2, wB0, wB1, wB2;
            float4 hA, hB;
            {
                const float* p0 = wb;
                wA0 = *reinterpret_cast<const ulonglong2*>(p0);
                wA1 = *reinterpret_cast<const ulonglong2*>(p0 + HDIM);
                wA2 = *reinterpret_cast<const ulonglong2*>(p0 + 2 * HDIM);
                const float* p1 = wb + TH;
                wB0 = *reinterpret_cast<const ulonglong2*>(p1);
                wB1 = *reinterpret_cast<const ulonglong2*>(p1 + HDIM);
                wB2 = *reinterpret_cast<const ulonglong2*>(p1 + 2 * HDIM);
                hA = *reinterpret_cast<const float4*>(hc + hoff(0, rowgrp));
                hB = *reinterpret_cast<const float4*>(hc + hoff(1, rowgrp));
            }

            for (int k = 0; k < HDIM; k += 2) {
                // even body: use (wA,hA) for k, prefetch k+2
                int ka = (k + 2 < HDIM) ? k + 2 : 0;
                const float* pa = wb + ka * TH;
                ulonglong2 nA0 = *reinterpret_cast<const ulonglong2*>(pa);
                ulonglong2 nA1 = *reinterpret_cast<const ulonglong2*>(pa + HDIM);
                ulonglong2 nA2 = *reinterpret_cast<const ulonglong2*>(pa + 2 * HDIM);
                float4 nhA = *reinterpret_cast<const float4*>(hc + hoff(ka, rowgrp));
                FMABLK(hA, wA0, wA1, wA2);
                wA0 = nA0; wA1 = nA1; wA2 = nA2; hA = nhA;

                // odd body: use (wB,hB) for k+1, prefetch k+3
                int kb = (k + 3 < HDIM) ? k + 3 : 1;
                const float* pb = wb + kb * TH;
                ulonglong2 nB0 = *reinterpret_cast<const ulonglong2*>(pb);
                ulonglong2 nB1 = *reinterpret_cast<const ulonglong2*>(pb + HDIM);
                ulonglong2 nB2 = *reinterpret_cast<const ulonglong2*>(pb + 2 * HDIM);
                float4 nhB = *reinterpret_cast<const float4*>(hc + hoff(kb, rowgrp));
                FMABLK(hB, wB0, wB1, wB2);
                wB0 = nB0; wB1 = nB1; wB2 = nB2; hB = nhB;
            }

            // epilogue: 4 hidden units x 4 rows
            const int jb = pass * 128 + hg * 32 + csub * 4;
            #pragma unroll
            for (int hh = 0; hh < 4; ++hh) {
                const int j  = jb + hh;
                const int pb = parbase(j);
                float4 p0 = *reinterpret_cast<const float4*>(s_par + pb);
                float4 p1 = *reinterpret_cast<const float4*>(s_par + pb + 4);
                const int ho = hoff(j, rowgrp);
                float4 hold = *reinterpret_cast<const float4*>(hc + ho);
                const int pp = hh >> 1;
                float4 hnew;
                #pragma unroll
                for (int r = 0; r < 4; ++r) {
                    float2 vr = unpk(acc[r][0][pp]);
                    float2 vz = unpk(acc[r][1][pp]);
                    float2 vn = unpk(acc[r][2][pp]);
                    float ar = (hh & 1) ? vr.y : vr.x;
                    float az = (hh & 1) ? vz.y : vz.x;
                    float an = (hh & 1) ? vn.y : vn.x;
                    float ho_r = (r == 0) ? hold.x : (r == 1) ? hold.y
                               : (r == 2) ? hold.z : hold.w;
                    float hv = gate(ar, az, an, xv[r], ho_r, p0, p1);
                    if (r == 0) hnew.x = hv;
                    else if (r == 1) hnew.y = hv;
                    else if (r == 2) hnew.z = hv;
                    else hnew.w = hv;
                }
                *reinterpret_cast<float4*>(hn + ho) = hnew;
            }
        }
        // sync the 4 warps (128 threads) of this row-group before next step
        asm volatile("bar.sync %0, %1;" :: "r"(barid), "r"(128) : "memory");
    }

    __syncthreads();             // rows cross row-groups in the output GEMM
    const float* hfin = sm;      // SEQ even -> final h in buffer 0

    // out[b][p] = sum_k h[b][k] * W_out[p][k] + b_out[p]
    // warp wid handles rows wid*4..+4 (rowgrp == wid); lane -> {p,p+32,p+64}
    const int orow = blockIdx.x * TILE_B + wid * 4;
    float oacc[4][3];
    #pragma unroll
    for (int i = 0; i < 4; ++i)
        oacc[i][0] = oacc[i][1] = oacc[i][2] = 0.0f;

    for (int k = 0; k < HDIM; ++k) {
        const float w0 = g_WoutT[k * POUT + lane];
        const float w1 = g_WoutT[k * POUT + lane + 32];
        const float w2 = g_WoutT[k * POUT + lane + 64];
        float4 hv4 = *reinterpret_cast<const float4*>(hfin + hoff(k, wid));
        const float hr[4] = {hv4.x, hv4.y, hv4.z, hv4.w};
        #pragma unroll
        for (int i = 0; i < 4; ++i) {
            oacc[i][0] = fmaf(hr[i], w0, oacc[i][0]);
            oacc[i][1] = fmaf(hr[i], w1, oacc[i][1]);
            oacc[i][2] = fmaf(hr[i], w2, oacc[i][2]);
        }
    }
    const float bo0 = b_out[lane];
    const float bo1 = b_out[lane + 32];
    const float bo2 = b_out[lane + 64];
    #pragma unroll
    for (int i = 0; i < 4; ++i) {
        float* op = out + (size_t)(orow + i) * POUT;
        op[lane]      = oacc[i][0] + bo0;
        op[lane + 32] = oacc[i][1] + bo1;
        op[lane + 64] = oacc[i][2] + bo2;
    }
}

extern "C" void kernel_launch(void* const* d_in, const int* in_sizes, int n_in,
                              void* d_out, int out_size) {
    const float* x     = (const float*)d_in[0];
    const float* W_ih  = (const float*)d_in[1];
    const float* W_hh  = (const float*)d_in[2];
    const float* b_ih  = (const float*)d_in[3];
    const float* b_hh  = (const float*)d_in[4];
    const float* W_out = (const float*)d_in[5];
    const float* b_out = (const float*)d_in[6];
    float* out = (float*)d_out;

    const size_t smem = (size_t)(2 * HBUF + PARW) * sizeof(float); // 144 KB
    cudaFuncSetAttribute(gru_kernel,
                         cudaFuncAttributeMaxDynamicSharedMemorySize, (int)smem);

    transpose_kernel<<<256, 256>>>(W_hh, W_out);
    gru_kernel<<<NCTA, NTHREADS, smem>>>(x, W_ih, b_ih, b_hh, b_out, out);
}

// round 11
// speedup vs baseline: 1.2609x; 1.1259x over previous
#include <cuda_runtime.h>
#include <cstdint>

// Problem constants
#define B_ROWS 8192
#define SEQ    512
#define HDIM   256
#define TH     768          // 3*H
#define POUT   96

// Tiling
#define TILE_B   64
#define NCTA     (B_ROWS / TILE_B)   // 128
#define NTHREADS 512
#define KW       64                  // words per hidden-unit column of h ([k][row])
#define HBUF     (HDIM * KW)         // 16384 floats per h buffer
#define PARW     4096                // swizzled gate-param table (words)
#define CHUNK_K  16                  // k-values per staged weight chunk
#define NCHUNK   (HDIM / CHUNK_K)    // 16
#define CWORDS   (CHUNK_K * 384)     // 6144 words per chunk (384 = 3 gates x 128 cols)

// Scratch (device globals; no allocation at runtime)
__device__ __align__(16) float g_Wt[HDIM * TH];      // Wt[k][3H] = W_hh[j][k]
__device__ __align__(16) float g_WoutT[HDIM * POUT]; // WoutT[k][p] = W_out[p][k]
__device__ __align__(16) float g_xT[SEQ * B_ROWS];   // xT[t][b]

// ---------------- packed f32x2 helpers ----------------
__device__ __forceinline__ void fma2(unsigned long long& d,
                                     unsigned long long a,
                                     unsigned long long b) {
    asm("fma.rn.f32x2 %0, %1, %2, %0;" : "+l"(d) : "l"(a), "l"(b));
}
__device__ __forceinline__ unsigned long long dup2(float w) {
    unsigned long long r;
    unsigned int u = __float_as_uint(w);
    asm("mov.b64 %0, {%1, %1};" : "=l"(r) : "r"(u));
    return r;
}
__device__ __forceinline__ float2 unpk(unsigned long long v) {
    unsigned int lo, hi;
    asm("mov.b64 {%0, %1}, %2;" : "=r"(lo), "=r"(hi) : "l"(v));
    return make_float2(__uint_as_float(lo), __uint_as_float(hi));
}

// ---------------- cp.async ----------------
__device__ __forceinline__ uint32_t smem_u32(const void* p) {
    uint32_t a;
    asm("{ .reg .u64 t; cvta.to.shared.u64 t, %1; cvt.u32.u64 %0, t; }"
        : "=r"(a) : "l"(p));
    return a;
}
__device__ __forceinline__ void cpasync16(uint32_t dst, const float* src) {
    asm volatile("cp.async.cg.shared.global [%0], [%1], 16;\n"
                 :: "r"(dst), "l"(src));
}
#define CP_COMMIT() asm volatile("cp.async.commit_group;\n" ::: "memory")
#define CP_WAIT1()  asm volatile("cp.async.wait_group 1;\n" ::: "memory")
#define CP_WAIT0()  asm volatile("cp.async.wait_group 0;\n" ::: "memory")

// ---------------- fast, accurate-enough nonlinearities ----------------
__device__ __forceinline__ float sigm(float x) {
    return __fdividef(1.0f, 1.0f + __expf(-x));
}
__device__ __forceinline__ float tanhfast(float x) {
    return __fdividef(2.0f, 1.0f + __expf(-2.0f * x)) - 1.0f;
}

// word offset of the float4 holding rows [rowgrp*4 .. +4) of hidden column k
__device__ __forceinline__ int hoff(int k, int rowgrp) {
    return k * KW + ((rowgrp ^ ((k >> 2) & 15)) << 2);
}
// base word of the 7-float param record of hidden unit j (bank-swizzled)
__device__ __forceinline__ int parbase(int j) {
    int c = j >> 2;
    return c * 64 + ((c & 7) << 2) + ((j & 3) << 3);
}

// ---------------- pre-kernels ----------------
__global__ void transpose_kernel(const float* __restrict__ W_hh,
                                 const float* __restrict__ W_out) {
    int idx = blockIdx.x * blockDim.x + threadIdx.x;
    int stride = gridDim.x * blockDim.x;
    for (int i = idx; i < HDIM * TH; i += stride) {
        int k = i / TH, j = i - k * TH;
        g_Wt[i] = W_hh[j * HDIM + k];
    }
    for (int i = idx; i < HDIM * POUT; i += stride) {
        int k = i / POUT, p = i - k * POUT;
        g_WoutT[i] = W_out[p * HDIM + k];
    }
}

// tiled transpose x[b][t] -> xT[t][b], both sides coalesced
__global__ void xpose_kernel(const float* __restrict__ x) {
    __shared__ float tile[32][33];
    int tx = threadIdx.x, ty = threadIdx.y;
    int t0 = blockIdx.x * 32;   // over SEQ
    int b0 = blockIdx.y * 32;   // over B_ROWS
    tile[ty][tx] = x[(size_t)(b0 + ty) * SEQ + t0 + tx];
    __syncthreads();
    g_xT[(size_t)(t0 + ty) * B_ROWS + b0 + tx] = tile[tx][ty];
}

// gate update with pre-packed params p0={wir,wiz,win,br}, p1={bz,bin,bhn,_}
__device__ __forceinline__ float gate(
    float a_r, float a_z, float a_n, float xval, float hold,
    float4 p0, float4 p1)
{
    float rg = sigm(fmaf(xval, p0.x, p0.w) + a_r);
    float zg = sigm(fmaf(xval, p0.y, p1.x) + a_z);
    float ng = tanhfast(fmaf(xval, p0.z, p1.y) + rg * (a_n + p1.z));
    return ng + zg * (hold - ng);
}

#define FMABLK(HV, W0, W1, W2)                                              \
    do {                                                                    \
        unsigned long long h0 = dup2((HV).x), h1 = dup2((HV).y);            \
        unsigned long long h2 = dup2((HV).z), h3 = dup2((HV).w);            \
        fma2(acc[0][0][0], h0, (W0).x); fma2(acc[0][0][1], h0, (W0).y);     \
        fma2(acc[1][0][0], h1, (W0).x); fma2(acc[1][0][1], h1, (W0).y);     \
        fma2(acc[2][0][0], h2, (W0).x); fma2(acc[2][0][1], h2, (W0).y);     \
        fma2(acc[3][0][0], h3, (W0).x); fma2(acc[3][0][1], h3, (W0).y);     \
        fma2(acc[0][1][0], h0, (W1).x); fma2(acc[0][1][1], h0, (W1).y);     \
        fma2(acc[1][1][0], h1, (W1).x); fma2(acc[1][1][1], h1, (W1).y);     \
        fma2(acc[2][1][0], h2, (W1).x); fma2(acc[2][1][1], h2, (W1).y);     \
        fma2(acc[3][1][0], h3, (W1).x); fma2(acc[3][1][1], h3, (W1).y);     \
        fma2(acc[0][2][0], h0, (W2).x); fma2(acc[0][2][1], h0, (W2).y);     \
        fma2(acc[1][2][0], h1, (W2).x); fma2(acc[1][2][1], h1, (W2).y);     \
        fma2(acc[2][2][0], h2, (W2).x); fma2(acc[2][2][1], h2, (W2).y);     \
        fma2(acc[3][2][0], h3, (W2).x); fma2(acc[3][2][1], h3, (W2).y);     \
    } while (0)

// ---------------- main persistent GRU kernel ----------------
__global__ void __launch_bounds__(NTHREADS, 1)
gru_kernel(const float* __restrict__ W_ih,
           const float* __restrict__ b_ih,
           const float* __restrict__ b_hh,
           const float* __restrict__ b_out,
           float* __restrict__ out)
{
    extern __shared__ float sm[];
    float* s_par = sm + 2 * HBUF;
    float* s_w   = s_par + PARW;          // 3 x CWORDS staging buffers
    const uint32_t s_w_addr = smem_u32(s_w);

    const int tid    = threadIdx.x;
    const int wid    = tid >> 5;
    const int lane   = tid & 31;
    const int rg     = wid >> 2;        // row group 0..3
    const int hg     = wid & 3;         // hidden group 0..3 (=SMSP)
    const int rsub   = lane & 3;        // row subchunk within group
    const int csub   = lane >> 2;       // hidden subchunk 0..7
    const int rowgrp = rg * 4 + rsub;   // 0..15 -> rows rowgrp*4..+4
    const int grow   = blockIdx.x * TILE_B + rowgrp * 4;

    // per-thread cp.async map: 1536 float4 per chunk, 3 per thread
    int soff[3], doff[3];
    #pragma unroll
    for (int i = 0; i < 3; ++i) {
        int f = tid + i * NTHREADS;
        int row = f / 96, rem = f - row * 96;
        int g = rem >> 5, c4 = rem & 31;
        soff[i] = row * TH + g * HDIM + c4 * 4;   // word offset in g_Wt slice
        doff[i] = (row * 384 + g * 128 + c4 * 4) * 4; // byte offset in chunk
    }

    // init gate-param table (biases pre-combined) and h buffers
    for (int j = tid; j < HDIM; j += NTHREADS) {
        int pb = parbase(j);
        s_par[pb + 0] = W_ih[j];
        s_par[pb + 1] = W_ih[HDIM + j];
        s_par[pb + 2] = W_ih[2 * HDIM + j];
        s_par[pb + 3] = b_ih[j] + b_hh[j];
        s_par[pb + 4] = b_ih[HDIM + j] + b_hh[HDIM + j];
        s_par[pb + 5] = b_ih[2 * HDIM + j];
        s_par[pb + 6] = b_hh[2 * HDIM + j];
    }
    for (int i = tid; i < 2 * HBUF; i += NTHREADS) sm[i] = 0.0f;  // h0 = 0
    __syncthreads();

    const int lwoff = hg * 32 + csub * 4;   // lane's word offset within a gate slice

    for (int t = 0; t < SEQ; ++t) {
        float* hc = sm + ((t & 1) ? HBUF : 0);
        float* hn = sm + ((t & 1) ? 0 : HBUF);

        // one coalesced float4 of x per warp (xT layout)
        const float4 xf = *reinterpret_cast<const float4*>(
            g_xT + (size_t)t * B_ROWS + grow);
        const float xv[4] = {xf.x, xf.y, xf.z, xf.w};

        #pragma unroll
        for (int pass = 0; pass < 2; ++pass) {
            const float* wsrc = g_Wt + pass * 128;   // this pass's 128-col half

            unsigned long long acc[4][3][2];
            #pragma unroll
            for (int r = 0; r < 4; ++r)
                #pragma unroll
                for (int g = 0; g < 3; ++g) {
                    acc[r][g][0] = 0ull; acc[r][g][1] = 0ull;
                }

            // prologue: protect buffers from previous pass, issue chunks 0,1
            __syncthreads();
            {
                const float* s0 = wsrc;
                #pragma unroll
                for (int i = 0; i < 3; ++i)
                    cpasync16(s_w_addr + doff[i], s0 + soff[i]);
                CP_COMMIT();
                const float* s1 = wsrc + CHUNK_K * TH;
                #pragma unroll
                for (int i = 0; i < 3; ++i)
                    cpasync16(s_w_addr + CWORDS * 4 + doff[i], s1 + soff[i]);
                CP_COMMIT();
            }

            for (int kc = 0; kc < NCHUNK; ++kc) {
                if (kc < NCHUNK - 1) { CP_WAIT1(); } else { CP_WAIT0(); }
                __syncthreads();   // chunk kc visible to all; kc-1 consumed by all

                const float* wc = s_w + (kc % 3) * CWORDS + lwoff;

                // consume 16 k's with depth-1 prefetch (wraps within chunk)
                ulonglong2 w0 = *reinterpret_cast<const ulonglong2*>(wc);
                ulonglong2 w1 = *reinterpret_cast<const ulonglong2*>(wc + 128);
                ulonglong2 w2 = *reinterpret_cast<const ulonglong2*>(wc + 256);
                float4 hv = *reinterpret_cast<const float4*>(
                    hc + hoff(kc * CHUNK_K, rowgrp));

                #pragma unroll 4
                for (int kl = 0; kl < CHUNK_K; ++kl) {
                    const int kn = (kl + 1) & (CHUNK_K - 1);
                    const float* wr = wc + kn * 384;
                    ulonglong2 n0 = *reinterpret_cast<const ulonglong2*>(wr);
                    ulonglong2 n1 = *reinterpret_cast<const ulonglong2*>(wr + 128);
                    ulonglong2 n2 = *reinterpret_cast<const ulonglong2*>(wr + 256);
                    float4 nh = *reinterpret_cast<const float4*>(
                        hc + hoff(kc * CHUNK_K + kn, rowgrp));
                    FMABLK(hv, w0, w1, w2);
                    w0 = n0; w1 = n1; w2 = n2; hv = nh;
                }

                // issue chunk kc+2 (its buffer held kc-1, consumed by all)
                if (kc + 2 < NCHUNK) {
                    const float* sN = wsrc + (kc + 2) * CHUNK_K * TH;
                    uint32_t dN = s_w_addr + (uint32_t)((kc + 2) % 3) * CWORDS * 4;
                    #pragma unroll
                    for (int i = 0; i < 3; ++i)
                        cpasync16(dN + doff[i], sN + soff[i]);
                    CP_COMMIT();
                }
            }

            // epilogue: 4 hidden units x 4 rows
            const int jb = pass * 128 + hg * 32 + csub * 4;
            #pragma unroll
            for (int hh = 0; hh < 4; ++hh) {
                const int j  = jb + hh;
                const int pb = parbase(j);
                float4 p0 = *reinterpret_cast<const float4*>(s_par + pb);
                float4 p1 = *reinterpret_cast<const float4*>(s_par + pb + 4);
                const int ho = hoff(j, rowgrp);
                float4 hold = *reinterpret_cast<const float4*>(hc + ho);
                const int pp = hh >> 1;
                float4 hnew;
                #pragma unroll
                for (int r = 0; r < 4; ++r) {
                    float2 vr = unpk(acc[r][0][pp]);
                    float2 vz = unpk(acc[r][1][pp]);
                    float2 vn = unpk(acc[r][2][pp]);
                    float ar = (hh & 1) ? vr.y : vr.x;
                    float az = (hh & 1) ? vz.y : vz.x;
                    float an = (hh & 1) ? vn.y : vn.x;
                    float ho_r = (r == 0) ? hold.x : (r == 1) ? hold.y
                               : (r == 2) ? hold.z : hold.w;
                    float hv2 = gate(ar, az, an, xv[r], ho_r, p0, p1);
                    if (r == 0) hnew.x = hv2;
                    else if (r == 1) hnew.y = hv2;
                    else if (r == 2) hnew.z = hv2;
                    else hnew.w = hv2;
                }
                *reinterpret_cast<float4*>(hn + ho) = hnew;
            }
        }
        // no per-step barrier needed: next step's pass-0 prologue barrier orders h
    }

    __syncthreads();             // rows cross row-groups in the output GEMM
    const float* hfin = sm;      // SEQ even -> final h in buffer 0

    // out[b][p] = sum_k h[b][k] * W_out[p][k] + b_out[p]
    const int orow = blockIdx.x * TILE_B + wid * 4;
    float oacc[4][3];
    #pragma unroll
    for (int i = 0; i < 4; ++i)
        oacc[i][0] = oacc[i][1] = oacc[i][2] = 0.0f;

    for (int k = 0; k < HDIM; ++k) {
        const float w0 = g_WoutT[k * POUT + lane];
        const float w1 = g_WoutT[k * POUT + lane + 32];
        const float w2 = g_WoutT[k * POUT + lane + 64];
        float4 hv4 = *reinterpret_cast<const float4*>(hfin + hoff(k, wid));
        const float hr[4] = {hv4.x, hv4.y, hv4.z, hv4.w};
        #pragma unroll
        for (int i = 0; i < 4; ++i) {
            oacc[i][0] = fmaf(hr[i], w0, oacc[i][0]);
            oacc[i][1] = fmaf(hr[i], w1, oacc[i][1]);
            oacc[i][2] = fmaf(hr[i], w2, oacc[i][2]);
        }
    }
    const float bo0 = b_out[lane];
    const float bo1 = b_out[lane + 32];
    const float bo2 = b_out[lane + 64];
    #pragma unroll
    for (int i = 0; i < 4; ++i) {
        float* op = out + (size_t)(orow + i) * POUT;
        op[lane]      = oacc[i][0] + bo0;
        op[lane + 32] = oacc[i][1] + bo1;
        op[lane + 64] = oacc[i][2] + bo2;
    }
}

extern "C" void kernel_launch(void* const* d_in, const int* in_sizes, int n_in,
                              void* d_out, int out_size) {
    const float* x     = (const float*)d_in[0];
    const float* W_ih  = (const float*)d_in[1];
    const float* W_hh  = (const float*)d_in[2];
    const float* b_ih  = (const float*)d_in[3];
    const float* b_hh  = (const float*)d_in[4];
    const float* W_out = (const float*)d_in[5];
    const float* b_out = (const float*)d_in[6];
    float* out = (float*)d_out;

    const size_t smem = (size_t)(2 * HBUF + PARW + 3 * CWORDS) * sizeof(float); // 216 KB
    cudaFuncSetAttribute(gru_kernel,
                         cudaFuncAttributeMaxDynamicSharedMemorySize, (int)smem);

    transpose_kernel<<<256, 256>>>(W_hh, W_out);
    dim3 xb(32, 32), xg(SEQ / 32, B_ROWS / 32);
    xpose_kernel<<<xg, xb>>>(x);
    gru_kernel<<<NCTA, NTHREADS, smem>>>(W_ih, b_ih, b_hh, b_out, out);
}

// round 12
// speedup vs baseline: 1.2634x; 1.0020x over previous
#include <cuda_runtime.h>
#include <cstdint>

// Problem constants
#define B_ROWS 8192
#define SEQ    512
#define HDIM   256
#define TH     768          // 3*H
#define POUT   96

// Tiling
#define TILE_B   64
#define NCTA     (B_ROWS / TILE_B)   // 128
#define NTHREADS 512
#define KW       64                  // words per hidden-unit column of h ([k][row])
#define HBUF     (HDIM * KW)         // 16384 floats per h buffer
#define PARW     4096                // swizzled gate-param table (words)
#define CHUNK_K  16                  // k-values per staged weight chunk
#define NCHUNK   (HDIM / CHUNK_K)    // 16
#define CWORDS   (CHUNK_K * 384)     // 6144 words per chunk (384 = 3 gates x 128 cols)

// Scratch (device globals; no allocation at runtime)
__device__ __align__(16) float g_Wt[HDIM * TH];      // Wt[k][3H] = W_hh[j][k]
__device__ __align__(16) float g_WoutT[HDIM * POUT]; // WoutT[k][p] = W_out[p][k]
__device__ __align__(16) float g_xT[SEQ * B_ROWS];   // xT[t][b]

// ---------------- packed f32x2 helpers ----------------
__device__ __forceinline__ void fma2(unsigned long long& d,
                                     unsigned long long a,
                                     unsigned long long b) {
    asm("fma.rn.f32x2 %0, %1, %2, %0;" : "+l"(d) : "l"(a), "l"(b));
}
__device__ __forceinline__ unsigned long long dup2(float w) {
    unsigned long long r;
    unsigned int u = __float_as_uint(w);
    asm("mov.b64 %0, {%1, %1};" : "=l"(r) : "r"(u));
    return r;
}
__device__ __forceinline__ float2 unpk(unsigned long long v) {
    unsigned int lo, hi;
    asm("mov.b64 {%0, %1}, %2;" : "=r"(lo), "=r"(hi) : "l"(v));
    return make_float2(__uint_as_float(lo), __uint_as_float(hi));
}

// ---------------- cp.async ----------------
__device__ __forceinline__ uint32_t smem_u32(const void* p) {
    uint32_t a;
    asm("{ .reg .u64 t; cvta.to.shared.u64 t, %1; cvt.u32.u64 %0, t; }"
        : "=r"(a) : "l"(p));
    return a;
}
__device__ __forceinline__ void cpasync16(uint32_t dst, const float* src) {
    asm volatile("cp.async.cg.shared.global [%0], [%1], 16;\n"
                 :: "r"(dst), "l"(src));
}
#define CP_COMMIT() asm volatile("cp.async.commit_group;\n" ::: "memory")
#define CP_WAIT1()  asm volatile("cp.async.wait_group 1;\n" ::: "memory")
#define CP_WAIT0()  asm volatile("cp.async.wait_group 0;\n" ::: "memory")

// ---------------- fast, accurate-enough nonlinearities ----------------
__device__ __forceinline__ float sigm(float x) {
    return __fdividef(1.0f, 1.0f + __expf(-x));
}
__device__ __forceinline__ float tanhfast(float x) {
    return __fdividef(2.0f, 1.0f + __expf(-2.0f * x)) - 1.0f;
}

// word offset of the float4 holding rows [rowgrp*4 .. +4) of hidden column k
__device__ __forceinline__ int hoff(int k, int rowgrp) {
    return k * KW + ((rowgrp ^ ((k >> 2) & 15)) << 2);
}
// base word of the 7-float param record of hidden unit j (bank-swizzled)
__device__ __forceinline__ int parbase(int j) {
    int c = j >> 2;
    return c * 64 + ((c & 7) << 2) + ((j & 3) << 3);
}

// ---------------- pre-kernels ----------------
__global__ void transpose_kernel(const float* __restrict__ W_hh,
                                 const float* __restrict__ W_out) {
    int idx = blockIdx.x * blockDim.x + threadIdx.x;
    int stride = gridDim.x * blockDim.x;
    for (int i = idx; i < HDIM * TH; i += stride) {
        int k = i / TH, j = i - k * TH;
        g_Wt[i] = W_hh[j * HDIM + k];
    }
    for (int i = idx; i < HDIM * POUT; i += stride) {
        int k = i / POUT, p = i - k * POUT;
        g_WoutT[i] = W_out[p * HDIM + k];
    }
}

// tiled transpose x[b][t] -> xT[t][b], both sides coalesced
__global__ void xpose_kernel(const float* __restrict__ x) {
    __shared__ float tile[32][33];
    int tx = threadIdx.x, ty = threadIdx.y;
    int t0 = blockIdx.x * 32;   // over SEQ
    int b0 = blockIdx.y * 32;   // over B_ROWS
    tile[ty][tx] = x[(size_t)(b0 + ty) * SEQ + t0 + tx];
    __syncthreads();
    g_xT[(size_t)(t0 + ty) * B_ROWS + b0 + tx] = tile[tx][ty];
}

// gate update with pre-packed params p0={wir,wiz,win,br}, p1={bz,bin,bhn,_}
__device__ __forceinline__ float gate(
    float a_r, float a_z, float a_n, float xval, float hold,
    float4 p0, float4 p1)
{
    float rg = sigm(fmaf(xval, p0.x, p0.w) + a_r);
    float zg = sigm(fmaf(xval, p0.y, p1.x) + a_z);
    float ng = tanhfast(fmaf(xval, p0.z, p1.y) + rg * (a_n + p1.z));
    return ng + zg * (hold - ng);
}

#define FMABLK(HV, W0, W1, W2)                                              \
    do {                                                                    \
        unsigned long long h0 = dup2((HV).x), h1 = dup2((HV).y);            \
        unsigned long long h2 = dup2((HV).z), h3 = dup2((HV).w);            \
        fma2(acc[0][0][0], h0, (W0).x); fma2(acc[0][0][1], h0, (W0).y);     \
        fma2(acc[1][0][0], h1, (W0).x); fma2(acc[1][0][1], h1, (W0).y);     \
        fma2(acc[2][0][0], h2, (W0).x); fma2(acc[2][0][1], h2, (W0).y);     \
        fma2(acc[3][0][0], h3, (W0).x); fma2(acc[3][0][1], h3, (W0).y);     \
        fma2(acc[0][1][0], h0, (W1).x); fma2(acc[0][1][1], h0, (W1).y);     \
        fma2(acc[1][1][0], h1, (W1).x); fma2(acc[1][1][1], h1, (W1).y);     \
        fma2(acc[2][1][0], h2, (W1).x); fma2(acc[2][1][1], h2, (W1).y);     \
        fma2(acc[3][1][0], h3, (W1).x); fma2(acc[3][1][1], h3, (W1).y);     \
        fma2(acc[0][2][0], h0, (W2).x); fma2(acc[0][2][1], h0, (W2).y);     \
        fma2(acc[1][2][0], h1, (W2).x); fma2(acc[1][2][1], h1, (W2).y);     \
        fma2(acc[2][2][0], h2, (W2).x); fma2(acc[2][2][1], h2, (W2).y);     \
        fma2(acc[3][2][0], h3, (W2).x); fma2(acc[3][2][1], h3, (W2).y);     \
    } while (0)

// ---------------- main persistent GRU kernel ----------------
__global__ void __launch_bounds__(NTHREADS, 1)
gru_kernel(const float* __restrict__ W_ih,
           const float* __restrict__ b_ih,
           const float* __restrict__ b_hh,
           const float* __restrict__ b_out,
           float* __restrict__ out)
{
    extern __shared__ float sm[];
    float* s_par = sm + 2 * HBUF;
    float* s_w   = s_par + PARW;          // 3 x CWORDS staging buffers
    const uint32_t s_w_addr = smem_u32(s_w);

    const int tid    = threadIdx.x;
    const int wid    = tid >> 5;
    const int lane   = tid & 31;
    const int rg     = wid >> 2;        // row group 0..3
    const int hg     = wid & 3;         // hidden group 0..3 (=SMSP)
    const int rsub   = lane & 3;        // row subchunk within group
    const int csub   = lane >> 2;       // hidden subchunk 0..7
    const int rowgrp = rg * 4 + rsub;   // 0..15 -> rows rowgrp*4..+4
    const int grow   = blockIdx.x * TILE_B + rowgrp * 4;

    // per-thread cp.async map: 1536 float4 per chunk, 3 per thread
    int soff[3], doff[3];
    #pragma unroll
    for (int i = 0; i < 3; ++i) {
        int f = tid + i * NTHREADS;
        int row = f / 96, rem = f - row * 96;
        int g = rem >> 5, c4 = rem & 31;
        soff[i] = row * TH + g * HDIM + c4 * 4;   // word offset in g_Wt slice
        doff[i] = (row * 384 + g * 128 + c4 * 4) * 4; // byte offset in chunk
    }

    // init gate-param table (biases pre-combined) and h buffers
    for (int j = tid; j < HDIM; j += NTHREADS) {
        int pb = parbase(j);
        s_par[pb + 0] = W_ih[j];
        s_par[pb + 1] = W_ih[HDIM + j];
        s_par[pb + 2] = W_ih[2 * HDIM + j];
        s_par[pb + 3] = b_ih[j] + b_hh[j];
        s_par[pb + 4] = b_ih[HDIM + j] + b_hh[HDIM + j];
        s_par[pb + 5] = b_ih[2 * HDIM + j];
        s_par[pb + 6] = b_hh[2 * HDIM + j];
    }
    for (int i = tid; i < 2 * HBUF; i += NTHREADS) sm[i] = 0.0f;  // h0 = 0
    __syncthreads();

    const int lwoff = hg * 32 + csub * 4;   // lane's word offset within a gate slice

    for (int t = 0; t < SEQ; ++t) {
        float* hc = sm + ((t & 1) ? HBUF : 0);
        float* hn = sm + ((t & 1) ? 0 : HBUF);

        // one coalesced float4 of x per warp (xT layout)
        const float4 xf = *reinterpret_cast<const float4*>(
            g_xT + (size_t)t * B_ROWS + grow);
        const float xv[4] = {xf.x, xf.y, xf.z, xf.w};

        #pragma unroll
        for (int pass = 0; pass < 2; ++pass) {
            const float* wsrc = g_Wt + pass * 128;   // this pass's 128-col half

            unsigned long long acc[4][3][2];
            #pragma unroll
            for (int r = 0; r < 4; ++r)
                #pragma unroll
                for (int g = 0; g < 3; ++g) {
                    acc[r][g][0] = 0ull; acc[r][g][1] = 0ull;
                }

            // prologue: protect buffers from previous pass, issue chunks 0,1
            __syncthreads();
            {
                const float* s0 = wsrc;
                #pragma unroll
                for (int i = 0; i < 3; ++i)
                    cpasync16(s_w_addr + doff[i], s0 + soff[i]);
                CP_COMMIT();
                const float* s1 = wsrc + CHUNK_K * TH;
                #pragma unroll
                for (int i = 0; i < 3; ++i)
                    cpasync16(s_w_addr + CWORDS * 4 + doff[i], s1 + soff[i]);
                CP_COMMIT();
            }

            for (int kc = 0; kc < NCHUNK; ++kc) {
                if (kc < NCHUNK - 1) { CP_WAIT1(); } else { CP_WAIT0(); }
                __syncthreads();   // chunk kc visible to all; kc-1 consumed by all

                const float* wc = s_w + (kc % 3) * CWORDS + lwoff;

                // consume 16 k's with depth-1 prefetch (wraps within chunk)
                ulonglong2 w0 = *reinterpret_cast<const ulonglong2*>(wc);
                ulonglong2 w1 = *reinterpret_cast<const ulonglong2*>(wc + 128);
                ulonglong2 w2 = *reinterpret_cast<const ulonglong2*>(wc + 256);
                float4 hv = *reinterpret_cast<const float4*>(
                    hc + hoff(kc * CHUNK_K, rowgrp));

                #pragma unroll 4
                for (int kl = 0; kl < CHUNK_K; ++kl) {
                    const int kn = (kl + 1) & (CHUNK_K - 1);
                    const float* wr = wc + kn * 384;
                    ulonglong2 n0 = *reinterpret_cast<const ulonglong2*>(wr);
                    ulonglong2 n1 = *reinterpret_cast<const ulonglong2*>(wr + 128);
                    ulonglong2 n2 = *reinterpret_cast<const ulonglong2*>(wr + 256);
                    float4 nh = *reinterpret_cast<const float4*>(
                        hc + hoff(kc * CHUNK_K + kn, rowgrp));
                    FMABLK(hv, w0, w1, w2);
                    w0 = n0; w1 = n1; w2 = n2; hv = nh;
                }

                // issue chunk kc+2 (its buffer held kc-1, consumed by all)
                if (kc + 2 < NCHUNK) {
                    const float* sN = wsrc + (kc + 2) * CHUNK_K * TH;
                    uint32_t dN = s_w_addr + (uint32_t)((kc + 2) % 3) * CWORDS * 4;
                    #pragma unroll
                    for (int i = 0; i < 3; ++i)
                        cpasync16(dN + doff[i], sN + soff[i]);
                    CP_COMMIT();
                }
            }

            // epilogue: 4 hidden units x 4 rows
            const int jb = pass * 128 + hg * 32 + csub * 4;
            #pragma unroll
            for (int hh = 0; hh < 4; ++hh) {
                const int j  = jb + hh;
                const int pb = parbase(j);
                float4 p0 = *reinterpret_cast<const float4*>(s_par + pb);
                float4 p1 = *reinterpret_cast<const float4*>(s_par + pb + 4);
                const int ho = hoff(j, rowgrp);
                float4 hold = *reinterpret_cast<const float4*>(hc + ho);
                const int pp = hh >> 1;
                float4 hnew;
                #pragma unroll
                for (int r = 0; r < 4; ++r) {
                    float2 vr = unpk(acc[r][0][pp]);
                    float2 vz = unpk(acc[r][1][pp]);
                    float2 vn = unpk(acc[r][2][pp]);
                    float ar = (hh & 1) ? vr.y : vr.x;
                    float az = (hh & 1) ? vz.y : vz.x;
                    float an = (hh & 1) ? vn.y : vn.x;
                    float ho_r = (r == 0) ? hold.x : (r == 1) ? hold.y
                               : (r == 2) ? hold.z : hold.w;
                    float hv2 = gate(ar, az, an, xv[r], ho_r, p0, p1);
                    if (r == 0) hnew.x = hv2;
                    else if (r == 1) hnew.y = hv2;
                    else if (r == 2) hnew.z = hv2;
                    else hnew.w = hv2;
                }
                *reinterpret_cast<float4*>(hn + ho) = hnew;
            }
        }
        // no per-step barrier needed: next step's pass-0 prologue barrier orders h
    }

    __syncthreads();             // rows cross row-groups in the output GEMM
    const float* hfin = sm;      // SEQ even -> final h in buffer 0

    // out[b][p] = sum_k h[b][k] * W_out[p][k] + b_out[p]
    const int orow = blockIdx.x * TILE_B + wid * 4;
    float oacc[4][3];
    #pragma unroll
    for (int i = 0; i < 4; ++i)
        oacc[i][0] = oacc[i][1] = oacc[i][2] = 0.0f;

    for (int k = 0; k < HDIM; ++k) {
        const float w0 = g_WoutT[k * POUT + lane];
        const float w1 = g_WoutT[k * POUT + lane + 32];
        const float w2 = g_WoutT[k * POUT + lane + 64];
        float4 hv4 = *reinterpret_cast<const float4*>(hfin + hoff(k, wid));
        const float hr[4] = {hv4.x, hv4.y, hv4.z, hv4.w};
        #pragma unroll
        for (int i = 0; i < 4; ++i) {
            oacc[i][0] = fmaf(hr[i], w0, oacc[i][0]);
            oacc[i][1] = fmaf(hr[i], w1, oacc[i][1]);
            oacc[i][2] = fmaf(hr[i], w2, oacc[i][2]);
        }
    }
    const float bo0 = b_out[lane];
    const float bo1 = b_out[lane + 32];
    const float bo2 = b_out[lane + 64];
    #pragma unroll
    for (int i = 0; i < 4; ++i) {
        float* op = out + (size_t)(orow + i) * POUT;
        op[lane]      = oacc[i][0] + bo0;
        op[lane + 32] = oacc[i][1] + bo1;
        op[lane + 64] = oacc[i][2] + bo2;
    }
}

extern "C" void kernel_launch(void* const* d_in, const int* in_sizes, int n_in,
                              void* d_out, int out_size) {
    const float* x     = (const float*)d_in[0];
    const float* W_ih  = (const float*)d_in[1];
    const float* W_hh  = (const float*)d_in[2];
    const float* b_ih  = (const float*)d_in[3];
    const float* b_hh  = (const float*)d_in[4];
    const float* W_out = (const float*)d_in[5];
    const float* b_out = (const float*)d_in[6];
    float* out = (float*)d_out;

    const size_t smem = (size_t)(2 * HBUF + PARW + 3 * CWORDS) * sizeof(float); // 216 KB
    cudaFuncSetAttribute(gru_kernel,
                         cudaFuncAttributeMaxDynamicSharedMemorySize, (int)smem);

    transpose_kernel<<<256, 256>>>(W_hh, W_out);
    dim3 xb(32, 32), xg(SEQ / 32, B_ROWS / 32);
    xpose_kernel<<<xg, xb>>>(x);
    gru_kernel<<<NCTA, NTHREADS, smem>>>(W_ih, b_ih, b_hh, b_out, out);
}